// round 13
// baseline (speedup 1.0000x reference)
#include <cuda_runtime.h>
#include <math.h>

#define VOCAB 50000
#define D 300
#define S 5
#define CTX 10
#define B 16384
#define XCOLS (2 + CTX)

#define THREADS 128
#define NBLOCKS (B * 32 / THREADS)   // one warp per batch element -> 4096 blocks

// Zero at module load; last block resets after each use -> graph-replay safe.
__device__ float g_acc[S];
__device__ unsigned int g_ticket;

__global__ __launch_bounds__(THREADS) void sense_fused_kernel(
    const int* __restrict__ x,
    const float* __restrict__ Wg,
    const float* __restrict__ Ws,
    float* __restrict__ out)
{
    const int gwarp = (blockIdx.x * THREADS + threadIdx.x) >> 5;
    const int lane  = threadIdx.x & 31;

    __shared__ float ssum[S];
    if (threadIdx.x < S) ssum[threadIdx.x] = 0.0f;
    __syncthreads();

    float p[S] = {0.f, 0.f, 0.f, 0.f, 0.f};

    {
        // x row is 12 ints = 48 B, 16B-aligned -> 3 int4 loads.
        const int4* xq = (const int4*)(x + (size_t)gwarp * XCOLS);
        const int4 q0 = __ldg(&xq[0]);   // x0, x1, c0, c1
        const int4 q1 = __ldg(&xq[1]);   // c2..c5
        const int4 q2 = __ldg(&xq[2]);   // c6..c9
        const int x0 = q0.x;
        int w[CTX] = {q0.z, q0.w, q1.x, q1.y, q1.z, q1.w, q2.x, q2.y, q2.z, q2.w};

        const float4* gr[CTX];
        #pragma unroll
        for (int j = 0; j < CTX; j++)
            gr[j] = (const float4*)(Wg + (size_t)w[j] * D);
        const float4* sr[S];
        #pragma unroll
        for (int s = 0; s < S; s++)
            sr[s] = (const float4*)(Ws + ((size_t)x0 * S + s) * D);

        // Chunk-major: per chunk, issue all 15 independent LDG.128s, then compute.
        #pragma unroll
        for (int c = 0; c < 3; c++) {
            const int off = c * 32 + lane;
            const bool act = (off < 75);           // 75 float4 per 300-float row
            float4 tg[CTX];
            float4 ts[S];
            #pragma unroll
            for (int j = 0; j < CTX; j++)
                tg[j] = act ? gr[j][off] : make_float4(0.f, 0.f, 0.f, 0.f);
            #pragma unroll
            for (int s = 0; s < S; s++)
                ts[s] = act ? sr[s][off] : make_float4(0.f, 0.f, 0.f, 0.f);

            float4 ctx = tg[0];
            #pragma unroll
            for (int j = 1; j < CTX; j++) {
                ctx.x += tg[j].x; ctx.y += tg[j].y;
                ctx.z += tg[j].z; ctx.w += tg[j].w;
            }
            #pragma unroll
            for (int s = 0; s < S; s++)
                p[s] += ts[s].x * ctx.x + ts[s].y * ctx.y
                      + ts[s].z * ctx.z + ts[s].w * ctx.w;
        }
    }

    // warp reduce each sense score
    #pragma unroll
    for (int s = 0; s < S; s++) {
        float v = p[s];
        #pragma unroll
        for (int o = 16; o > 0; o >>= 1)
            v += __shfl_xor_sync(0xFFFFFFFFu, v, o);
        p[s] = v;
    }

    // block combine via shared atomics (4 warps x 5)
    if (lane == 0) {
        #pragma unroll
        for (int s = 0; s < S; s++)
            atomicAdd(&ssum[s], p[s]);
    }
    __syncthreads();

    // Global accumulate with CONSUMED return: the ATOMG result-wait guarantees
    // this block's add completed at L2 before we pass the barrier below, so the
    // ticket order is provably after the accumulate. No fences.
    float old = 0.0f;
    if (threadIdx.x < S)
        old = atomicAdd(&g_acc[threadIdx.x], ssum[threadIdx.x]);
    // keep `old` live so the compiler can't demote ATOMG -> REDG
    if (threadIdx.x < S) ssum[threadIdx.x] = old;
    __syncthreads();

    __shared__ bool is_last;
    if (threadIdx.x == 0)
        is_last = (atomicAdd(&g_ticket, 1u) == (unsigned int)(NBLOCKS - 1));
    __syncthreads();

    if (is_last && threadIdx.x < S) {
        float v = atomicAdd(&g_acc[threadIdx.x], 0.0f);   // L2-path read
        out[threadIdx.x] = 1.0f / (1.0f + expf(-v));
        atomicExch(&g_acc[threadIdx.x], 0.0f);            // reset for replay
        if (threadIdx.x == 0) atomicExch(&g_ticket, 0u);
    }
}

extern "C" void kernel_launch(void* const* d_in, const int* in_sizes, int n_in,
                              void* d_out, int out_size) {
    const int*   x  = (const int*)d_in[0];
    const float* Wg = (const float*)d_in[1];
    const float* Ws = (const float*)d_in[2];
    float* out = (float*)d_out;

    sense_fused_kernel<<<NBLOCKS, THREADS>>>(x, Wg, Ws, out);
}